// round 13
// baseline (speedup 1.0000x reference)
#include <cuda_runtime.h>
#include <cuda_fp16.h>
#include <math.h>

#define NN   100000
#define NNP  100096
#define EE   1600000
#define HID  128
#define DIN  6
#define OUTD 2
#define SLOPE 0.2f

#define SCAN_B 1024
#define NB ((NN + SCAN_B - 1) / SCAN_B)   // 98
#define FULLM 0xffffffffu

// ---------------- device scratch ----------------
__device__ __half g_hh  [NN  * HID];
__device__ __half g_h1h [NNP * HID];
__device__ __half g_hxh [NNP * HID];
__device__ unsigned int g_wfrag[16 * 8 * 32 * 2];
__device__ float  g_asrc [NN];
__device__ float  g_adst [NN];
__device__ float  g_ind  [NNP];
__device__ float  g_denom[NN];
__device__ uint2  g_edge [EE];         // {src, exp_bits} CSR order
__device__ int    g_eidA [EE];
__device__ float  g_alphan[EE];
__device__ int    g_counts [NN];
__device__ int    g_offsets[NN + 1];
__device__ int    g_cursor [NN];
__device__ int    g_bsum   [NB];
__device__ float  g_cedge;
__device__ float  g_was6[DIN];
__device__ float  g_wad6[DIN];
__device__ int    g_is64;

__device__ __forceinline__ float4 h4_to_f4(uint2 r) {
    __half2 h0 = *reinterpret_cast<__half2*>(&r.x);
    __half2 h1 = *reinterpret_cast<__half2*>(&r.y);
    float2 f0 = __half22float2(h0);
    float2 f1 = __half22float2(h1);
    return make_float4(f0.x, f0.y, f1.x, f1.y);
}
__device__ __forceinline__ uint2 f4_to_h4(float4 v) {
    __half2 p0 = __floats2half2_rn(v.x, v.y);
    __half2 p1 = __floats2half2_rn(v.z, v.w);
    uint2 st;
    st.x = *reinterpret_cast<unsigned int*>(&p0);
    st.y = *reinterpret_cast<unsigned int*>(&p1);
    return st;
}

// ---------------- pre-pass ----------------
__global__ void k_pre(const int* __restrict__ ei32,
                      const float* __restrict__ w_edge,
                      const float* __restrict__ att_edge,
                      const float* __restrict__ w_gat,
                      const float* __restrict__ att_src,
                      const float* __restrict__ att_dst) {
    int i = blockIdx.x * blockDim.x + threadIdx.x;
    if (i < NN) { g_counts[i] = 0; g_denom[i] = 0.f; }

    if (blockIdx.x == 0) {
        __shared__ int nz;
        if (threadIdx.x == 0) nz = 0;
        __syncthreads();
        int found = 0;
        for (int t = threadIdx.x; t < 4096; t += blockDim.x)
            if (ei32[2 * t + 1] != 0) found = 1;
        if (found) atomicAdd(&nz, 1);
        __syncthreads();
        if (threadIdx.x == 0) g_is64 = (nz == 0) ? 1 : 0;
    } else if (blockIdx.x == 1 && threadIdx.x < 128) {
        int j = threadIdx.x;
        if (j == 0) {
            g_cedge = 0.f;
            for (int k = 0; k < DIN; k++) { g_was6[k] = 0.f; g_wad6[k] = 0.f; }
        }
        __syncthreads();
        float as = att_src[j], ad = att_dst[j];
        float vce = w_edge[j] * att_edge[j];
        float vas[DIN], vad[DIN];
#pragma unroll
        for (int k = 0; k < DIN; k++) {
            float wg = w_gat[k * HID + j];
            vas[k] = wg * as;
            vad[k] = wg * ad;
        }
#pragma unroll
        for (int o = 16; o > 0; o >>= 1) {
            vce += __shfl_xor_sync(FULLM, vce, o);
#pragma unroll
            for (int k = 0; k < DIN; k++) {
                vas[k] += __shfl_xor_sync(FULLM, vas[k], o);
                vad[k] += __shfl_xor_sync(FULLM, vad[k], o);
            }
        }
        if ((j & 31) == 0) {
            atomicAdd(&g_cedge, vce);
#pragma unroll
            for (int k = 0; k < DIN; k++) {
                atomicAdd(&g_was6[k], vas[k]);
                atomicAdd(&g_wad6[k], vad[k]);
            }
        }
    }
}

__global__ void k_wprep(const float* __restrict__ w_gcn) {
    int t = blockIdx.x * blockDim.x + threadIdx.x;
    int nt = t >> 8, ks = (t >> 5) & 7, lane = t & 31;
    int k0 = ks * 16 + (lane & 3) * 2;
    int n  = nt * 8 + (lane >> 2);
    __half2 b0 = __floats2half2_rn(w_gcn[k0 * HID + n], w_gcn[(k0 + 1) * HID + n]);
    __half2 b1 = __floats2half2_rn(w_gcn[(k0 + 8) * HID + n], w_gcn[(k0 + 9) * HID + n]);
    int idx = ((nt * 8 + ks) * 32 + lane) * 2;
    g_wfrag[idx]     = *reinterpret_cast<unsigned int*>(&b0);
    g_wfrag[idx + 1] = *reinterpret_cast<unsigned int*>(&b1);
}

__global__ void k_convert(const void* __restrict__ ei) {
    int e = blockIdx.x * blockDim.x + threadIdx.x;
    if (e >= EE) return;
    int d;
    if (g_is64) d = (int)((const long long*)ei)[EE + e];
    else        d = ((const int*)ei)[EE + e];
    atomicAdd(&g_counts[d], 1);
}

// warp handles 4 nodes: w_gat cached in registers; no reductions; high occupancy
__global__ __launch_bounds__(256) void k_node_transform(
    const float* __restrict__ x, const float* __restrict__ w_gat) {
    int warp = blockIdx.x * 8 + (threadIdx.x >> 5);
    int lane = threadIdx.x & 31;

    float4 wreg[DIN];
#pragma unroll
    for (int k = 0; k < DIN; k++)
        wreg[k] = *(const float4*)&w_gat[k * HID + lane * 4];

    int n0 = warp * 4;
#pragma unroll
    for (int t = 0; t < 4; t++) {
        int n = n0 + t;
        if (n >= NN) return;
        float xr[DIN];
#pragma unroll
        for (int k = 0; k < DIN; k++) xr[k] = x[n * DIN + k];
        float4 acc = make_float4(0.f, 0.f, 0.f, 0.f);
#pragma unroll
        for (int k = 0; k < DIN; k++) {
            acc.x += xr[k] * wreg[k].x; acc.y += xr[k] * wreg[k].y;
            acc.z += xr[k] * wreg[k].z; acc.w += xr[k] * wreg[k].w;
        }
        *(uint2*)&g_hh[(size_t)n * HID + lane * 4] = f4_to_h4(acc);
        if (lane == 0) {
            float asum = 0.f, dsum = 0.f;
#pragma unroll
            for (int k = 0; k < DIN; k++) {
                asum += xr[k] * g_was6[k];
                dsum += xr[k] * g_wad6[k];
            }
            g_asrc[n] = asum;
            g_adst[n] = dsum;
        }
    }
}

// per-block sums of counts (for the fused scan)
__global__ void k_bsum() {
    __shared__ int s4[8];
    int b = blockIdx.x;
    int tid = threadIdx.x;                 // 256 threads, 4 counts each
    int v = 0;
#pragma unroll
    for (int k = 0; k < 4; k++) {
        int gi = b * SCAN_B + tid + k * 256;
        v += (gi < NN) ? g_counts[gi] : 0;
    }
#pragma unroll
    for (int o = 16; o > 0; o >>= 1) v += __shfl_xor_sync(FULLM, v, o);
    if ((tid & 31) == 0) s4[tid >> 5] = v;
    __syncthreads();
    if (tid == 0) {
        int t = 0;
#pragma unroll
        for (int k = 0; k < 8; k++) t += s4[k];
        g_bsum[b] = t;
    }
}

// fused scan: local smem scan + prefix-from-bsums + all writes
__global__ void k_scanall() {
    __shared__ int s[SCAN_B];
    __shared__ int spre;
    int tid = threadIdx.x;
    if (tid == 0) spre = 0;
    __syncthreads();
    if (tid < NB && tid < blockIdx.x) atomicAdd(&spre, g_bsum[tid]);

    int gi = blockIdx.x * SCAN_B + tid;
    int cnt = (gi < NN) ? g_counts[gi] : 0;
    s[tid] = cnt;
    __syncthreads();
    for (int off = 1; off < SCAN_B; off <<= 1) {
        int t = (tid >= off) ? s[tid - off] : 0;
        __syncthreads();
        s[tid] += t;
        __syncthreads();
    }
    int pre = spre;
    if (gi < NN) {
        int o = s[tid] - cnt + pre;        // exclusive + block prefix
        g_offsets[gi] = o;
        g_cursor[gi]  = o;
        g_ind[gi]     = (cnt > 0) ? 1.f : 0.f;
    }
    if (gi == 0) g_offsets[NN] = EE;
}

// scatter: 2 edges/thread, vectorized index loads
__global__ void k_scatter(const void* __restrict__ ei, const float* __restrict__ ew,
                          int need_eid) {
    int e = (blockIdx.x * blockDim.x + threadIdx.x) * 2;
    if (e >= EE) return;
    int s0, d0, s1, d1;
    if (g_is64) {
        const longlong2* ps = (const longlong2*)((const long long*)ei + e);
        const longlong2* pd = (const longlong2*)((const long long*)ei + EE + e);
        longlong2 sv = *ps, dv = *pd;
        s0 = (int)sv.x; s1 = (int)sv.y;
        d0 = (int)dv.x; d1 = (int)dv.y;
    } else {
        int2 sv = *(const int2*)((const int*)ei + e);
        int2 dv = *(const int2*)((const int*)ei + EE + e);
        s0 = sv.x; s1 = sv.y;
        d0 = dv.x; d1 = dv.y;
    }
    float2 w2 = *(const float2*)&ew[e];
    float ce = g_cedge;

    float l0 = g_asrc[s0] + g_adst[d0] + ce * w2.x;
    l0 = (l0 > 0.f) ? l0 : SLOPE * l0;
    float ev0 = __expf(l0);
    int p0 = atomicAdd(&g_cursor[d0], 1);
    g_edge[p0] = make_uint2((unsigned int)s0, (unsigned int)__float_as_int(ev0));
    atomicAdd(&g_denom[d0], ev0);
    if (need_eid) g_eidA[p0] = e;

    float l1 = g_asrc[s1] + g_adst[d1] + ce * w2.y;
    l1 = (l1 > 0.f) ? l1 : SLOPE * l1;
    float ev1 = __expf(l1);
    int p1 = atomicAdd(&g_cursor[d1], 1);
    g_edge[p1] = make_uint2((unsigned int)s1, (unsigned int)__float_as_int(ev1));
    atomicAdd(&g_denom[d1], ev1);
    if (need_eid) g_eidA[p1] = e + 1;
}

// warp per dst node: GAT aggregation
__global__ __launch_bounds__(256) void k_gat(const float* __restrict__ b_gat,
                                             int need_alpha) {
    int n = blockIdx.x * 8 + (threadIdx.x >> 5);
    if (n >= NN) return;
    int lane = threadIdx.x & 31;
    int off = g_offsets[n];
    int deg = g_offsets[n + 1] - off;
    float invd = 1.f / fmaxf(g_denom[n], 1e-16f);

    float4 acc = make_float4(0.f, 0.f, 0.f, 0.f);
    int i = 0;
    for (; i + 4 <= deg; i += 4) {
        uint2 e0 = g_edge[off + i];
        uint2 e1 = g_edge[off + i + 1];
        uint2 e2 = g_edge[off + i + 2];
        uint2 e3 = g_edge[off + i + 3];
        uint2 r0 = *(const uint2*)&g_hh[(size_t)e0.x * HID + lane * 4];
        uint2 r1 = *(const uint2*)&g_hh[(size_t)e1.x * HID + lane * 4];
        uint2 r2 = *(const uint2*)&g_hh[(size_t)e2.x * HID + lane * 4];
        uint2 r3 = *(const uint2*)&g_hh[(size_t)e3.x * HID + lane * 4];
        float a0 = __int_as_float(e0.y), a1 = __int_as_float(e1.y);
        float a2 = __int_as_float(e2.y), a3 = __int_as_float(e3.y);
        float4 f0 = h4_to_f4(r0), f1 = h4_to_f4(r1);
        float4 f2 = h4_to_f4(r2), f3 = h4_to_f4(r3);
        acc.x += a0 * f0.x + a1 * f1.x + a2 * f2.x + a3 * f3.x;
        acc.y += a0 * f0.y + a1 * f1.y + a2 * f2.y + a3 * f3.y;
        acc.z += a0 * f0.z + a1 * f1.z + a2 * f2.z + a3 * f3.z;
        acc.w += a0 * f0.w + a1 * f1.w + a2 * f2.w + a3 * f3.w;
    }
    for (; i < deg; i++) {
        uint2 e0 = g_edge[off + i];
        uint2 r0 = *(const uint2*)&g_hh[(size_t)e0.x * HID + lane * 4];
        float a0 = __int_as_float(e0.y);
        float4 f0 = h4_to_f4(r0);
        acc.x += a0 * f0.x; acc.y += a0 * f0.y;
        acc.z += a0 * f0.z; acc.w += a0 * f0.w;
    }

    float4 b4 = *(const float4*)&b_gat[lane * 4];
    float4 r;
    r.x = fmaxf(acc.x * invd + b4.x, 0.f);
    r.y = fmaxf(acc.y * invd + b4.y, 0.f);
    r.z = fmaxf(acc.z * invd + b4.z, 0.f);
    r.w = fmaxf(acc.w * invd + b4.w, 0.f);
    *(uint2*)&g_h1h[(size_t)n * HID + lane * 4] = f4_to_h4(r);

    if (need_alpha) {
        for (int j = lane; j < deg; j += 32)
            g_alphan[off + j] = __int_as_float(g_edge[off + j].y) * invd;
    }
}

// hx = ind[row] * (h1 @ w_gcn) via mma.sync m16n8k16
__global__ __launch_bounds__(256) void k_gemm_mma() {
    int base = blockIdx.x * 128;
    int w    = threadIdx.x >> 5;
    int lane = threadIdx.x & 31;
    int gid  = lane >> 2;
    int k0   = (lane & 3) * 2;
    int nr = base + w * 16 + gid;

    unsigned int A[8][4];
#pragma unroll
    for (int ks = 0; ks < 8; ks++) {
        int kc = ks * 16 + k0;
        A[ks][0] = *(const unsigned int*)&g_h1h[(size_t)nr * HID + kc];
        A[ks][1] = *(const unsigned int*)&g_h1h[(size_t)(nr + 8) * HID + kc];
        A[ks][2] = *(const unsigned int*)&g_h1h[(size_t)nr * HID + kc + 8];
        A[ks][3] = *(const unsigned int*)&g_h1h[(size_t)(nr + 8) * HID + kc + 8];
    }

    float ind0 = g_ind[nr];
    float ind1 = g_ind[nr + 8];

#pragma unroll
    for (int nt = 0; nt < 16; nt++) {
        float c0 = 0.f, c1 = 0.f, c2 = 0.f, c3 = 0.f;
#pragma unroll
        for (int ks = 0; ks < 8; ks++) {
            int idx = ((nt * 8 + ks) * 32 + lane) * 2;
            unsigned int b0 = g_wfrag[idx];
            unsigned int b1 = g_wfrag[idx + 1];
            asm volatile(
                "mma.sync.aligned.m16n8k16.row.col.f32.f16.f16.f32 "
                "{%0,%1,%2,%3}, {%4,%5,%6,%7}, {%8,%9}, {%0,%1,%2,%3};"
                : "+f"(c0), "+f"(c1), "+f"(c2), "+f"(c3)
                : "r"(A[ks][0]), "r"(A[ks][1]), "r"(A[ks][2]), "r"(A[ks][3]),
                  "r"(b0), "r"(b1));
        }
        int col = nt * 8 + k0;
        if (nr < NN) {
            __half2 p = __floats2half2_rn(c0 * ind0, c1 * ind0);
            *(unsigned int*)&g_hxh[(size_t)nr * HID + col] =
                *reinterpret_cast<unsigned int*>(&p);
        }
        if (nr + 8 < NN) {
            __half2 p = __floats2half2_rn(c2 * ind1, c3 * ind1);
            *(unsigned int*)&g_hxh[(size_t)(nr + 8) * HID + col] =
                *reinterpret_cast<unsigned int*>(&p);
        }
    }
}

// warp per dst node: GCN aggregation + head
__global__ __launch_bounds__(256) void k_gcn_out(
    const float* __restrict__ b_gcn, const float* __restrict__ w_out,
    const float* __restrict__ b_out, float* __restrict__ out) {
    int n = blockIdx.x * 8 + (threadIdx.x >> 5);
    if (n >= NN) return;
    int lane = threadIdx.x & 31;
    int off = g_offsets[n];
    int deg = g_offsets[n + 1] - off;
    float invd = 1.f / fmaxf(g_denom[n], 1e-16f);

    float4 acc = make_float4(0.f, 0.f, 0.f, 0.f);
    int i = 0;
    for (; i + 4 <= deg; i += 4) {
        uint2 e0 = g_edge[off + i];
        uint2 e1 = g_edge[off + i + 1];
        uint2 e2 = g_edge[off + i + 2];
        uint2 e3 = g_edge[off + i + 3];
        uint2 r0 = *(const uint2*)&g_hxh[(size_t)e0.x * HID + lane * 4];
        uint2 r1 = *(const uint2*)&g_hxh[(size_t)e1.x * HID + lane * 4];
        uint2 r2 = *(const uint2*)&g_hxh[(size_t)e2.x * HID + lane * 4];
        uint2 r3 = *(const uint2*)&g_hxh[(size_t)e3.x * HID + lane * 4];
        float a0 = __int_as_float(e0.y), a1 = __int_as_float(e1.y);
        float a2 = __int_as_float(e2.y), a3 = __int_as_float(e3.y);
        float4 f0 = h4_to_f4(r0), f1 = h4_to_f4(r1);
        float4 f2 = h4_to_f4(r2), f3 = h4_to_f4(r3);
        acc.x += a0 * f0.x + a1 * f1.x + a2 * f2.x + a3 * f3.x;
        acc.y += a0 * f0.y + a1 * f1.y + a2 * f2.y + a3 * f3.y;
        acc.z += a0 * f0.z + a1 * f1.z + a2 * f2.z + a3 * f3.z;
        acc.w += a0 * f0.w + a1 * f1.w + a2 * f2.w + a3 * f3.w;
    }
    for (; i < deg; i++) {
        uint2 e0 = g_edge[off + i];
        uint2 r0 = *(const uint2*)&g_hxh[(size_t)e0.x * HID + lane * 4];
        float a0 = __int_as_float(e0.y);
        float4 f0 = h4_to_f4(r0);
        acc.x += a0 * f0.x; acc.y += a0 * f0.y;
        acc.z += a0 * f0.z; acc.w += a0 * f0.w;
    }

    float4 b4 = *(const float4*)&b_gcn[lane * 4];
    float4 h2;
    h2.x = fmaxf(acc.x * invd + b4.x, 0.f);
    h2.y = fmaxf(acc.y * invd + b4.y, 0.f);
    h2.z = fmaxf(acc.z * invd + b4.z, 0.f);
    h2.w = fmaxf(acc.w * invd + b4.w, 0.f);

    int jc = lane * 4;
    float v0 = h2.x * w_out[(jc + 0) * 2] + h2.y * w_out[(jc + 1) * 2]
             + h2.z * w_out[(jc + 2) * 2] + h2.w * w_out[(jc + 3) * 2];
    float v1 = h2.x * w_out[(jc + 0) * 2 + 1] + h2.y * w_out[(jc + 1) * 2 + 1]
             + h2.z * w_out[(jc + 2) * 2 + 1] + h2.w * w_out[(jc + 3) * 2 + 1];
#pragma unroll
    for (int o = 16; o > 0; o >>= 1) {
        v0 += __shfl_xor_sync(FULLM, v0, o);
        v1 += __shfl_xor_sync(FULLM, v1, o);
    }
    if (lane == 0) {
        out[n * 2 + 0] = v0 + b_out[0];
        out[n * 2 + 1] = v1 + b_out[1];
    }
}

__global__ void k_copy_ei_f(const void* __restrict__ ei, float* __restrict__ dst) {
    int i = blockIdx.x * blockDim.x + threadIdx.x;
    if (i >= 2 * EE) return;
    if (g_is64) dst[i] = (float)((const long long*)ei)[i];
    else        dst[i] = (float)((const int*)ei)[i];
}

__global__ void k_copy_alpha(float* __restrict__ dst) {
    int i = blockIdx.x * blockDim.x + threadIdx.x;
    if (i < EE) dst[g_eidA[i]] = g_alphan[i];
}

// ---------------- launch ----------------
extern "C" void kernel_launch(void* const* d_in, const int* in_sizes, int n_in,
                              void* d_out, int out_size) {
    int iei, iew, iwg, ias, iad, iwe, iae, ibg, iwgcn, ibgcn, iwo, ibo;
    if (in_sizes[1] == 2 * EE) {
        iei = 1; iew = 2; iwg = 3; ias = 4; iad = 5; iwe = 6; iae = 7;
        ibg = 8; iwgcn = 9; ibgcn = 10; iwo = 11; ibo = 12;
    } else {
        iew = 1; iwg = 2; ias = 3; iad = 4; iwe = 5; iae = 6; ibg = 7;
        iwgcn = 8; ibgcn = 9; iwo = 10; ibo = 11; iei = 12;
    }

    const float* x        = (const float*)d_in[0];
    const void*  ei       = d_in[iei];
    const float* ew       = (const float*)d_in[iew];
    const float* w_gat    = (const float*)d_in[iwg];
    const float* att_src  = (const float*)d_in[ias];
    const float* att_dst  = (const float*)d_in[iad];
    const float* w_edge   = (const float*)d_in[iwe];
    const float* att_edge = (const float*)d_in[iae];
    const float* b_gat    = (const float*)d_in[ibg];
    const float* w_gcn    = (const float*)d_in[iwgcn];
    const float* b_gcn    = (const float*)d_in[ibgcn];
    const float* w_out    = (const float*)d_in[iwo];
    const float* b_out    = (const float*)d_in[ibo];
    float*       out      = (float*)d_out;

    int rem = out_size - NN * OUTD;
    int need_alpha = (rem == EE || rem == 3 * EE) ? 1 : 0;

    k_pre<<<(NN + 255) / 256, 256>>>((const int*)ei, w_edge, att_edge,
                                     w_gat, att_src, att_dst);
    k_wprep<<<16, 256>>>(w_gcn);
    k_convert<<<(EE + 255) / 256, 256>>>(ei);
    k_node_transform<<<(NN + 31) / 32, 256>>>(x, w_gat);
    k_bsum<<<NB, 256>>>();
    k_scanall<<<NB, SCAN_B>>>();
    k_scatter<<<(EE / 2 + 255) / 256, 256>>>(ei, ew, need_alpha);
    k_gat<<<NN / 8, 256>>>(b_gat, need_alpha);
    k_gemm_mma<<<NNP / 128, 256>>>();
    k_gcn_out<<<NN / 8, 256>>>(b_gcn, w_out, b_out, out);

    if (rem == EE) {
        k_copy_alpha<<<(EE + 255) / 256, 256>>>(out + NN * OUTD);
    } else if (rem == 3 * EE) {
        k_copy_ei_f<<<(2 * EE + 255) / 256, 256>>>(ei, out + NN * OUTD);
        k_copy_alpha<<<(EE + 255) / 256, 256>>>(out + NN * OUTD + 2 * EE);
    }
}

// round 14
// speedup vs baseline: 1.0426x; 1.0426x over previous
#include <cuda_runtime.h>
#include <cuda_fp16.h>
#include <math.h>

#define NN   100000
#define NNP  100096
#define EE   1600000
#define HID  128
#define DIN  6
#define OUTD 2
#define SLOPE 0.2f

#define SCAN_B 1024
#define NB ((NN + SCAN_B - 1) / SCAN_B)   // 98
#define FULLM 0xffffffffu

// ---------------- device scratch ----------------
__device__ __half g_hh  [NN  * HID];
__device__ __half g_h1h [NNP * HID];
__device__ __half g_hxh [NNP * HID];
__device__ unsigned int g_wfrag[16 * 8 * 32 * 2];
__device__ float  g_asrc [NN];
__device__ float  g_adst [NN];
__device__ float  g_ind  [NNP];
__device__ float  g_invd [NN];         // 1/denom, written by k_gat
__device__ uint2  g_edge [EE];         // {src, exp_bits} CSR order
__device__ int    g_eidA [EE];
__device__ float  g_alphan[EE];
__device__ int    g_counts [NN];
__device__ int    g_offsets[NN + 1];
__device__ int    g_cursor [NN];
__device__ int    g_bsum   [NB];
__device__ float  g_cedge;
__device__ float  g_was6[DIN];
__device__ float  g_wad6[DIN];
__device__ int    g_is64;

__device__ __forceinline__ float4 h4_to_f4(uint2 r) {
    __half2 h0 = *reinterpret_cast<__half2*>(&r.x);
    __half2 h1 = *reinterpret_cast<__half2*>(&r.y);
    float2 f0 = __half22float2(h0);
    float2 f1 = __half22float2(h1);
    return make_float4(f0.x, f0.y, f1.x, f1.y);
}
__device__ __forceinline__ uint2 f4_to_h4(float4 v) {
    __half2 p0 = __floats2half2_rn(v.x, v.y);
    __half2 p1 = __floats2half2_rn(v.z, v.w);
    uint2 st;
    st.x = *reinterpret_cast<unsigned int*>(&p0);
    st.y = *reinterpret_cast<unsigned int*>(&p1);
    return st;
}

// ---------------- pre-pass ----------------
__global__ void k_pre(const int* __restrict__ ei32,
                      const float* __restrict__ w_edge,
                      const float* __restrict__ att_edge,
                      const float* __restrict__ w_gat,
                      const float* __restrict__ att_src,
                      const float* __restrict__ att_dst) {
    int i = blockIdx.x * blockDim.x + threadIdx.x;
    if (i < NN) g_counts[i] = 0;

    if (blockIdx.x == 0) {
        __shared__ int nz;
        if (threadIdx.x == 0) nz = 0;
        __syncthreads();
        int found = 0;
        for (int t = threadIdx.x; t < 4096; t += blockDim.x)
            if (ei32[2 * t + 1] != 0) found = 1;
        if (found) atomicAdd(&nz, 1);
        __syncthreads();
        if (threadIdx.x == 0) g_is64 = (nz == 0) ? 1 : 0;
    } else if (blockIdx.x == 1 && threadIdx.x < 128) {
        int j = threadIdx.x;
        if (j == 0) {
            g_cedge = 0.f;
            for (int k = 0; k < DIN; k++) { g_was6[k] = 0.f; g_wad6[k] = 0.f; }
        }
        __syncthreads();
        float as = att_src[j], ad = att_dst[j];
        float vce = w_edge[j] * att_edge[j];
        float vas[DIN], vad[DIN];
#pragma unroll
        for (int k = 0; k < DIN; k++) {
            float wg = w_gat[k * HID + j];
            vas[k] = wg * as;
            vad[k] = wg * ad;
        }
#pragma unroll
        for (int o = 16; o > 0; o >>= 1) {
            vce += __shfl_xor_sync(FULLM, vce, o);
#pragma unroll
            for (int k = 0; k < DIN; k++) {
                vas[k] += __shfl_xor_sync(FULLM, vas[k], o);
                vad[k] += __shfl_xor_sync(FULLM, vad[k], o);
            }
        }
        if ((j & 31) == 0) {
            atomicAdd(&g_cedge, vce);
#pragma unroll
            for (int k = 0; k < DIN; k++) {
                atomicAdd(&g_was6[k], vas[k]);
                atomicAdd(&g_wad6[k], vad[k]);
            }
        }
    }
}

__global__ void k_wprep(const float* __restrict__ w_gcn) {
    int t = blockIdx.x * blockDim.x + threadIdx.x;
    int nt = t >> 8, ks = (t >> 5) & 7, lane = t & 31;
    int k0 = ks * 16 + (lane & 3) * 2;
    int n  = nt * 8 + (lane >> 2);
    __half2 b0 = __floats2half2_rn(w_gcn[k0 * HID + n], w_gcn[(k0 + 1) * HID + n]);
    __half2 b1 = __floats2half2_rn(w_gcn[(k0 + 8) * HID + n], w_gcn[(k0 + 9) * HID + n]);
    int idx = ((nt * 8 + ks) * 32 + lane) * 2;
    g_wfrag[idx]     = *reinterpret_cast<unsigned int*>(&b0);
    g_wfrag[idx + 1] = *reinterpret_cast<unsigned int*>(&b1);
}

// histogram, 2 edges/thread
__global__ void k_convert(const void* __restrict__ ei) {
    int e = (blockIdx.x * blockDim.x + threadIdx.x) * 2;
    if (e >= EE) return;
    int d0, d1;
    if (g_is64) {
        longlong2 dv = *(const longlong2*)((const long long*)ei + EE + e);
        d0 = (int)dv.x; d1 = (int)dv.y;
    } else {
        int2 dv = *(const int2*)((const int*)ei + EE + e);
        d0 = dv.x; d1 = dv.y;
    }
    atomicAdd(&g_counts[d0], 1);
    atomicAdd(&g_counts[d1], 1);
}

// warp handles 4 nodes: pure h compute+store (asrc/adst moved to k_scanall)
__global__ __launch_bounds__(256) void k_node_transform(
    const float* __restrict__ x, const float* __restrict__ w_gat) {
    int warp = blockIdx.x * 8 + (threadIdx.x >> 5);
    int lane = threadIdx.x & 31;

    float4 wreg[DIN];
#pragma unroll
    for (int k = 0; k < DIN; k++)
        wreg[k] = *(const float4*)&w_gat[k * HID + lane * 4];

    int n0 = warp * 4;
#pragma unroll
    for (int t = 0; t < 4; t++) {
        int n = n0 + t;
        if (n >= NN) return;
        float4 acc = make_float4(0.f, 0.f, 0.f, 0.f);
#pragma unroll
        for (int k = 0; k < DIN; k++) {
            float xk = x[n * DIN + k];
            acc.x += xk * wreg[k].x; acc.y += xk * wreg[k].y;
            acc.z += xk * wreg[k].z; acc.w += xk * wreg[k].w;
        }
        *(uint2*)&g_hh[(size_t)n * HID + lane * 4] = f4_to_h4(acc);
    }
}

// per-block sums of counts
__global__ void k_bsum() {
    __shared__ int s4[8];
    int b = blockIdx.x;
    int tid = threadIdx.x;
    int v = 0;
#pragma unroll
    for (int k = 0; k < 4; k++) {
        int gi = b * SCAN_B + tid + k * 256;
        v += (gi < NN) ? g_counts[gi] : 0;
    }
#pragma unroll
    for (int o = 16; o > 0; o >>= 1) v += __shfl_xor_sync(FULLM, v, o);
    if ((tid & 31) == 0) s4[tid >> 5] = v;
    __syncthreads();
    if (tid == 0) {
        int t = 0;
#pragma unroll
        for (int k = 0; k < 8; k++) t += s4[k];
        g_bsum[b] = t;
    }
}

// fused scan + asrc/adst computation (node-parallel work hidden under scan barriers)
__global__ void k_scanall(const float* __restrict__ x) {
    __shared__ int s[SCAN_B];
    __shared__ int spre;
    int tid = threadIdx.x;
    if (tid == 0) spre = 0;
    __syncthreads();
    if (tid < NB && tid < blockIdx.x) atomicAdd(&spre, g_bsum[tid]);

    int gi = blockIdx.x * SCAN_B + tid;
    int cnt = (gi < NN) ? g_counts[gi] : 0;
    s[tid] = cnt;

    // asrc/adst (independent of the scan; overlaps the barriers below)
    float asum = 0.f, dsum = 0.f;
    if (gi < NN) {
#pragma unroll
        for (int k = 0; k < DIN; k++) {
            float xk = x[gi * DIN + k];
            asum += xk * g_was6[k];
            dsum += xk * g_wad6[k];
        }
    }

    __syncthreads();
    for (int off = 1; off < SCAN_B; off <<= 1) {
        int t = (tid >= off) ? s[tid - off] : 0;
        __syncthreads();
        s[tid] += t;
        __syncthreads();
    }
    int pre = spre;
    if (gi < NN) {
        int o = s[tid] - cnt + pre;
        g_offsets[gi] = o;
        g_cursor[gi]  = o;
        g_ind[gi]     = (cnt > 0) ? 1.f : 0.f;
        g_asrc[gi]    = asum;
        g_adst[gi]    = dsum;
    }
    if (gi == 0) g_offsets[NN] = EE;
}

// scatter + logit/exp; uint2 record; eid separate, only if alpha needed
__global__ void k_scatter(const void* __restrict__ ei, const float* __restrict__ ew,
                          int need_eid) {
    int e = blockIdx.x * blockDim.x + threadIdx.x;
    if (e >= EE) return;
    int s, d;
    if (g_is64) {
        const long long* p = (const long long*)ei;
        s = (int)p[e];
        d = (int)p[EE + e];
    } else {
        const int* p = (const int*)ei;
        s = p[e];
        d = p[EE + e];
    }
    float l = g_asrc[s] + g_adst[d] + g_cedge * ew[e];
    l = (l > 0.f) ? l : SLOPE * l;
    float ev = __expf(l);
    int pos = atomicAdd(&g_cursor[d], 1);
    g_edge[pos] = make_uint2((unsigned int)s, (unsigned int)__float_as_int(ev));
    if (need_eid) g_eidA[pos] = e;
}

// warp per dst node: denom pre-pass + GAT aggregation; stores invd for gcn pass
__global__ __launch_bounds__(256) void k_gat(const float* __restrict__ b_gat,
                                             int need_alpha) {
    int n = blockIdx.x * 8 + (threadIdx.x >> 5);
    if (n >= NN) return;
    int lane = threadIdx.x & 31;
    int off = g_offsets[n];
    int deg = g_offsets[n + 1] - off;

    float lsum = 0.f;
    for (int i = lane; i < deg; i += 32)
        lsum += __int_as_float(g_edge[off + i].y);
#pragma unroll
    for (int o = 16; o > 0; o >>= 1) lsum += __shfl_xor_sync(FULLM, lsum, o);
    float invd = 1.f / fmaxf(lsum, 1e-16f);
    if (lane == 0) g_invd[n] = invd;

    float4 acc = make_float4(0.f, 0.f, 0.f, 0.f);
    int i = 0;
    for (; i + 4 <= deg; i += 4) {
        uint2 e0 = g_edge[off + i];
        uint2 e1 = g_edge[off + i + 1];
        uint2 e2 = g_edge[off + i + 2];
        uint2 e3 = g_edge[off + i + 3];
        uint2 r0 = *(const uint2*)&g_hh[(size_t)e0.x * HID + lane * 4];
        uint2 r1 = *(const uint2*)&g_hh[(size_t)e1.x * HID + lane * 4];
        uint2 r2 = *(const uint2*)&g_hh[(size_t)e2.x * HID + lane * 4];
        uint2 r3 = *(const uint2*)&g_hh[(size_t)e3.x * HID + lane * 4];
        float a0 = __int_as_float(e0.y), a1 = __int_as_float(e1.y);
        float a2 = __int_as_float(e2.y), a3 = __int_as_float(e3.y);
        float4 f0 = h4_to_f4(r0), f1 = h4_to_f4(r1);
        float4 f2 = h4_to_f4(r2), f3 = h4_to_f4(r3);
        acc.x += a0 * f0.x + a1 * f1.x + a2 * f2.x + a3 * f3.x;
        acc.y += a0 * f0.y + a1 * f1.y + a2 * f2.y + a3 * f3.y;
        acc.z += a0 * f0.z + a1 * f1.z + a2 * f2.z + a3 * f3.z;
        acc.w += a0 * f0.w + a1 * f1.w + a2 * f2.w + a3 * f3.w;
    }
    for (; i < deg; i++) {
        uint2 e0 = g_edge[off + i];
        uint2 r0 = *(const uint2*)&g_hh[(size_t)e0.x * HID + lane * 4];
        float a0 = __int_as_float(e0.y);
        float4 f0 = h4_to_f4(r0);
        acc.x += a0 * f0.x; acc.y += a0 * f0.y;
        acc.z += a0 * f0.z; acc.w += a0 * f0.w;
    }

    float4 b4 = *(const float4*)&b_gat[lane * 4];
    float4 r;
    r.x = fmaxf(acc.x * invd + b4.x, 0.f);
    r.y = fmaxf(acc.y * invd + b4.y, 0.f);
    r.z = fmaxf(acc.z * invd + b4.z, 0.f);
    r.w = fmaxf(acc.w * invd + b4.w, 0.f);
    *(uint2*)&g_h1h[(size_t)n * HID + lane * 4] = f4_to_h4(r);

    if (need_alpha) {
        for (int j = lane; j < deg; j += 32)
            g_alphan[off + j] = __int_as_float(g_edge[off + j].y) * invd;
    }
}

// hx = ind[row] * (h1 @ w_gcn) via mma.sync m16n8k16
__global__ __launch_bounds__(256) void k_gemm_mma() {
    int base = blockIdx.x * 128;
    int w    = threadIdx.x >> 5;
    int lane = threadIdx.x & 31;
    int gid  = lane >> 2;
    int k0   = (lane & 3) * 2;
    int nr = base + w * 16 + gid;

    unsigned int A[8][4];
#pragma unroll
    for (int ks = 0; ks < 8; ks++) {
        int kc = ks * 16 + k0;
        A[ks][0] = *(const unsigned int*)&g_h1h[(size_t)nr * HID + kc];
        A[ks][1] = *(const unsigned int*)&g_h1h[(size_t)(nr + 8) * HID + kc];
        A[ks][2] = *(const unsigned int*)&g_h1h[(size_t)nr * HID + kc + 8];
        A[ks][3] = *(const unsigned int*)&g_h1h[(size_t)(nr + 8) * HID + kc + 8];
    }

    float ind0 = g_ind[nr];
    float ind1 = g_ind[nr + 8];

#pragma unroll
    for (int nt = 0; nt < 16; nt++) {
        float c0 = 0.f, c1 = 0.f, c2 = 0.f, c3 = 0.f;
#pragma unroll
        for (int ks = 0; ks < 8; ks++) {
            int idx = ((nt * 8 + ks) * 32 + lane) * 2;
            unsigned int b0 = g_wfrag[idx];
            unsigned int b1 = g_wfrag[idx + 1];
            asm volatile(
                "mma.sync.aligned.m16n8k16.row.col.f32.f16.f16.f32 "
                "{%0,%1,%2,%3}, {%4,%5,%6,%7}, {%8,%9}, {%0,%1,%2,%3};"
                : "+f"(c0), "+f"(c1), "+f"(c2), "+f"(c3)
                : "r"(A[ks][0]), "r"(A[ks][1]), "r"(A[ks][2]), "r"(A[ks][3]),
                  "r"(b0), "r"(b1));
        }
        int col = nt * 8 + k0;
        if (nr < NN) {
            __half2 p = __floats2half2_rn(c0 * ind0, c1 * ind0);
            *(unsigned int*)&g_hxh[(size_t)nr * HID + col] =
                *reinterpret_cast<unsigned int*>(&p);
        }
        if (nr + 8 < NN) {
            __half2 p = __floats2half2_rn(c2 * ind1, c3 * ind1);
            *(unsigned int*)&g_hxh[(size_t)(nr + 8) * HID + col] =
                *reinterpret_cast<unsigned int*>(&p);
        }
    }
}

// warp per dst node: GCN aggregation (invd from k_gat) + head
__global__ __launch_bounds__(256) void k_gcn_out(
    const float* __restrict__ b_gcn, const float* __restrict__ w_out,
    const float* __restrict__ b_out, float* __restrict__ out) {
    int n = blockIdx.x * 8 + (threadIdx.x >> 5);
    if (n >= NN) return;
    int lane = threadIdx.x & 31;
    int off = g_offsets[n];
    int deg = g_offsets[n + 1] - off;
    float invd = g_invd[n];

    float4 acc = make_float4(0.f, 0.f, 0.f, 0.f);
    int i = 0;
    for (; i + 4 <= deg; i += 4) {
        uint2 e0 = g_edge[off + i];
        uint2 e1 = g_edge[off + i + 1];
        uint2 e2 = g_edge[off + i + 2];
        uint2 e3 = g_edge[off + i + 3];
        uint2 r0 = *(const uint2*)&g_hxh[(size_t)e0.x * HID + lane * 4];
        uint2 r1 = *(const uint2*)&g_hxh[(size_t)e1.x * HID + lane * 4];
        uint2 r2 = *(const uint2*)&g_hxh[(size_t)e2.x * HID + lane * 4];
        uint2 r3 = *(const uint2*)&g_hxh[(size_t)e3.x * HID + lane * 4];
        float a0 = __int_as_float(e0.y), a1 = __int_as_float(e1.y);
        float a2 = __int_as_float(e2.y), a3 = __int_as_float(e3.y);
        float4 f0 = h4_to_f4(r0), f1 = h4_to_f4(r1);
        float4 f2 = h4_to_f4(r2), f3 = h4_to_f4(r3);
        acc.x += a0 * f0.x + a1 * f1.x + a2 * f2.x + a3 * f3.x;
        acc.y += a0 * f0.y + a1 * f1.y + a2 * f2.y + a3 * f3.y;
        acc.z += a0 * f0.z + a1 * f1.z + a2 * f2.z + a3 * f3.z;
        acc.w += a0 * f0.w + a1 * f1.w + a2 * f2.w + a3 * f3.w;
    }
    for (; i < deg; i++) {
        uint2 e0 = g_edge[off + i];
        uint2 r0 = *(const uint2*)&g_hxh[(size_t)e0.x * HID + lane * 4];
        float a0 = __int_as_float(e0.y);
        float4 f0 = h4_to_f4(r0);
        acc.x += a0 * f0.x; acc.y += a0 * f0.y;
        acc.z += a0 * f0.z; acc.w += a0 * f0.w;
    }

    float4 b4 = *(const float4*)&b_gcn[lane * 4];
    float4 h2;
    h2.x = fmaxf(acc.x * invd + b4.x, 0.f);
    h2.y = fmaxf(acc.y * invd + b4.y, 0.f);
    h2.z = fmaxf(acc.z * invd + b4.z, 0.f);
    h2.w = fmaxf(acc.w * invd + b4.w, 0.f);

    int jc = lane * 4;
    float v0 = h2.x * w_out[(jc + 0) * 2] + h2.y * w_out[(jc + 1) * 2]
             + h2.z * w_out[(jc + 2) * 2] + h2.w * w_out[(jc + 3) * 2];
    float v1 = h2.x * w_out[(jc + 0) * 2 + 1] + h2.y * w_out[(jc + 1) * 2 + 1]
             + h2.z * w_out[(jc + 2) * 2 + 1] + h2.w * w_out[(jc + 3) * 2 + 1];
#pragma unroll
    for (int o = 16; o > 0; o >>= 1) {
        v0 += __shfl_xor_sync(FULLM, v0, o);
        v1 += __shfl_xor_sync(FULLM, v1, o);
    }
    if (lane == 0) {
        out[n * 2 + 0] = v0 + b_out[0];
        out[n * 2 + 1] = v1 + b_out[1];
    }
}

__global__ void k_copy_ei_f(const void* __restrict__ ei, float* __restrict__ dst) {
    int i = blockIdx.x * blockDim.x + threadIdx.x;
    if (i >= 2 * EE) return;
    if (g_is64) dst[i] = (float)((const long long*)ei)[i];
    else        dst[i] = (float)((const int*)ei)[i];
}

__global__ void k_copy_alpha(float* __restrict__ dst) {
    int i = blockIdx.x * blockDim.x + threadIdx.x;
    if (i < EE) dst[g_eidA[i]] = g_alphan[i];
}

// ---------------- launch ----------------
extern "C" void kernel_launch(void* const* d_in, const int* in_sizes, int n_in,
                              void* d_out, int out_size) {
    int iei, iew, iwg, ias, iad, iwe, iae, ibg, iwgcn, ibgcn, iwo, ibo;
    if (in_sizes[1] == 2 * EE) {
        iei = 1; iew = 2; iwg = 3; ias = 4; iad = 5; iwe = 6; iae = 7;
        ibg = 8; iwgcn = 9; ibgcn = 10; iwo = 11; ibo = 12;
    } else {
        iew = 1; iwg = 2; ias = 3; iad = 4; iwe = 5; iae = 6; ibg = 7;
        iwgcn = 8; ibgcn = 9; iwo = 10; ibo = 11; iei = 12;
    }

    const float* x        = (const float*)d_in[0];
    const void*  ei       = d_in[iei];
    const float* ew       = (const float*)d_in[iew];
    const float* w_gat    = (const float*)d_in[iwg];
    const float* att_src  = (const float*)d_in[ias];
    const float* att_dst  = (const float*)d_in[iad];
    const float* w_edge   = (const float*)d_in[iwe];
    const float* att_edge = (const float*)d_in[iae];
    const float* b_gat    = (const float*)d_in[ibg];
    const float* w_gcn    = (const float*)d_in[iwgcn];
    const float* b_gcn    = (const float*)d_in[ibgcn];
    const float* w_out    = (const float*)d_in[iwo];
    const float* b_out    = (const float*)d_in[ibo];
    float*       out      = (float*)d_out;

    int rem = out_size - NN * OUTD;
    int need_alpha = (rem == EE || rem == 3 * EE) ? 1 : 0;

    k_pre<<<(NN + 255) / 256, 256>>>((const int*)ei, w_edge, att_edge,
                                     w_gat, att_src, att_dst);
    k_wprep<<<16, 256>>>(w_gcn);
    k_convert<<<(EE / 2 + 255) / 256, 256>>>(ei);
    k_node_transform<<<(NN + 31) / 32, 256>>>(x, w_gat);
    k_bsum<<<NB, 256>>>();
    k_scanall<<<NB, SCAN_B>>>(x);
    k_scatter<<<(EE + 255) / 256, 256>>>(ei, ew, need_alpha);
    k_gat<<<NN / 8, 256>>>(b_gat, need_alpha);
    k_gemm_mma<<<NNP / 128, 256>>>();
    k_gcn_out<<<NN / 8, 256>>>(b_gcn, w_out, b_out, out);

    if (rem == EE) {
        k_copy_alpha<<<(EE + 255) / 256, 256>>>(out + NN * OUTD);
    } else if (rem == 3 * EE) {
        k_copy_ei_f<<<(2 * EE + 255) / 256, 256>>>(ei, out + NN * OUTD);
        k_copy_alpha<<<(EE + 255) / 256, 256>>>(out + NN * OUTD + 2 * EE);
    }
}

// round 15
// speedup vs baseline: 1.0631x; 1.0196x over previous
#include <cuda_runtime.h>
#include <cuda_fp16.h>
#include <math.h>

#define NN   100000
#define NNP  100096
#define EE   1600000
#define HID  128
#define DIN  6
#define OUTD 2
#define SLOPE 0.2f

#define SCAN_B 1024
#define NB ((NN + SCAN_B - 1) / SCAN_B)   // 98
#define FULLM 0xffffffffu

// ---------------- device scratch ----------------
__device__ __half g_hh  [NN  * HID];
__device__ __half g_h1h [NNP * HID];
__device__ __half g_hxh [NNP * HID];
__device__ unsigned int g_wfrag[16 * 8 * 32 * 2];
__device__ float  g_asrc [NN];
__device__ float  g_adst [NN];
__device__ float  g_ind  [NNP];
__device__ float  g_invd [NN];
__device__ uint2  g_edge [EE];         // {src, exp_bits} CSR order
__device__ int    g_eidA [EE];
__device__ float  g_alphan[EE];
__device__ int    g_counts [NN];
__device__ int    g_offsets[NN + 1];
__device__ int    g_cursor [NN];
__device__ int    g_bsum   [NB];
__device__ float  g_cedge;
__device__ float  g_was6[DIN];
__device__ float  g_wad6[DIN];
__device__ int    g_is64;

__device__ __forceinline__ float4 h4_to_f4(uint2 r) {
    __half2 h0 = *reinterpret_cast<__half2*>(&r.x);
    __half2 h1 = *reinterpret_cast<__half2*>(&r.y);
    float2 f0 = __half22float2(h0);
    float2 f1 = __half22float2(h1);
    return make_float4(f0.x, f0.y, f1.x, f1.y);
}
__device__ __forceinline__ uint2 f4_to_h4(float4 v) {
    __half2 p0 = __floats2half2_rn(v.x, v.y);
    __half2 p1 = __floats2half2_rn(v.z, v.w);
    uint2 st;
    st.x = *reinterpret_cast<unsigned int*>(&p0);
    st.y = *reinterpret_cast<unsigned int*>(&p1);
    return st;
}

// ---------------- pre-pass ----------------
__global__ void k_pre(const int* __restrict__ ei32,
                      const float* __restrict__ w_edge,
                      const float* __restrict__ att_edge,
                      const float* __restrict__ w_gat,
                      const float* __restrict__ att_src,
                      const float* __restrict__ att_dst) {
    int i = blockIdx.x * blockDim.x + threadIdx.x;
    if (i < NN) g_counts[i] = 0;

    if (blockIdx.x == 0) {
        __shared__ int nz;
        if (threadIdx.x == 0) nz = 0;
        __syncthreads();
        int found = 0;
        for (int t = threadIdx.x; t < 4096; t += blockDim.x)
            if (ei32[2 * t + 1] != 0) found = 1;
        if (found) atomicAdd(&nz, 1);
        __syncthreads();
        if (threadIdx.x == 0) g_is64 = (nz == 0) ? 1 : 0;
    } else if (blockIdx.x == 1 && threadIdx.x < 128) {
        int j = threadIdx.x;
        if (j == 0) {
            g_cedge = 0.f;
            for (int k = 0; k < DIN; k++) { g_was6[k] = 0.f; g_wad6[k] = 0.f; }
        }
        __syncthreads();
        float as = att_src[j], ad = att_dst[j];
        float vce = w_edge[j] * att_edge[j];
        float vas[DIN], vad[DIN];
#pragma unroll
        for (int k = 0; k < DIN; k++) {
            float wg = w_gat[k * HID + j];
            vas[k] = wg * as;
            vad[k] = wg * ad;
        }
#pragma unroll
        for (int o = 16; o > 0; o >>= 1) {
            vce += __shfl_xor_sync(FULLM, vce, o);
#pragma unroll
            for (int k = 0; k < DIN; k++) {
                vas[k] += __shfl_xor_sync(FULLM, vas[k], o);
                vad[k] += __shfl_xor_sync(FULLM, vad[k], o);
            }
        }
        if ((j & 31) == 0) {
            atomicAdd(&g_cedge, vce);
#pragma unroll
            for (int k = 0; k < DIN; k++) {
                atomicAdd(&g_was6[k], vas[k]);
                atomicAdd(&g_wad6[k], vad[k]);
            }
        }
    }
}

__global__ void k_wprep(const float* __restrict__ w_gcn) {
    int t = blockIdx.x * blockDim.x + threadIdx.x;
    int nt = t >> 8, ks = (t >> 5) & 7, lane = t & 31;
    int k0 = ks * 16 + (lane & 3) * 2;
    int n  = nt * 8 + (lane >> 2);
    __half2 b0 = __floats2half2_rn(w_gcn[k0 * HID + n], w_gcn[(k0 + 1) * HID + n]);
    __half2 b1 = __floats2half2_rn(w_gcn[(k0 + 8) * HID + n], w_gcn[(k0 + 9) * HID + n]);
    int idx = ((nt * 8 + ks) * 32 + lane) * 2;
    g_wfrag[idx]     = *reinterpret_cast<unsigned int*>(&b0);
    g_wfrag[idx + 1] = *reinterpret_cast<unsigned int*>(&b1);
}

// histogram, 2 edges/thread
__global__ void k_convert(const void* __restrict__ ei) {
    int e = (blockIdx.x * blockDim.x + threadIdx.x) * 2;
    if (e >= EE) return;
    int d0, d1;
    if (g_is64) {
        longlong2 dv = *(const longlong2*)((const long long*)ei + EE + e);
        d0 = (int)dv.x; d1 = (int)dv.y;
    } else {
        int2 dv = *(const int2*)((const int*)ei + EE + e);
        d0 = dv.x; d1 = dv.y;
    }
    atomicAdd(&g_counts[d0], 1);
    atomicAdd(&g_counts[d1], 1);
}

// warp handles 4 nodes: pure h compute+store
__global__ __launch_bounds__(256) void k_node_transform(
    const float* __restrict__ x, const float* __restrict__ w_gat) {
    int warp = blockIdx.x * 8 + (threadIdx.x >> 5);
    int lane = threadIdx.x & 31;

    float4 wreg[DIN];
#pragma unroll
    for (int k = 0; k < DIN; k++)
        wreg[k] = *(const float4*)&w_gat[k * HID + lane * 4];

    int n0 = warp * 4;
#pragma unroll
    for (int t = 0; t < 4; t++) {
        int n = n0 + t;
        if (n >= NN) return;
        float4 acc = make_float4(0.f, 0.f, 0.f, 0.f);
#pragma unroll
        for (int k = 0; k < DIN; k++) {
            float xk = x[n * DIN + k];
            acc.x += xk * wreg[k].x; acc.y += xk * wreg[k].y;
            acc.z += xk * wreg[k].z; acc.w += xk * wreg[k].w;
        }
        *(uint2*)&g_hh[(size_t)n * HID + lane * 4] = f4_to_h4(acc);
    }
}

// per-block sums of counts
__global__ void k_bsum() {
    __shared__ int s4[8];
    int b = blockIdx.x;
    int tid = threadIdx.x;
    int v = 0;
#pragma unroll
    for (int k = 0; k < 4; k++) {
        int gi = b * SCAN_B + tid + k * 256;
        v += (gi < NN) ? g_counts[gi] : 0;
    }
#pragma unroll
    for (int o = 16; o > 0; o >>= 1) v += __shfl_xor_sync(FULLM, v, o);
    if ((tid & 31) == 0) s4[tid >> 5] = v;
    __syncthreads();
    if (tid == 0) {
        int t = 0;
#pragma unroll
        for (int k = 0; k < 8; k++) t += s4[k];
        g_bsum[b] = t;
    }
}

// fused scan + asrc/adst computation
__global__ void k_scanall(const float* __restrict__ x) {
    __shared__ int s[SCAN_B];
    __shared__ int spre;
    int tid = threadIdx.x;
    if (tid == 0) spre = 0;
    __syncthreads();
    if (tid < NB && tid < blockIdx.x) atomicAdd(&spre, g_bsum[tid]);

    int gi = blockIdx.x * SCAN_B + tid;
    int cnt = (gi < NN) ? g_counts[gi] : 0;
    s[tid] = cnt;

    float asum = 0.f, dsum = 0.f;
    if (gi < NN) {
#pragma unroll
        for (int k = 0; k < DIN; k++) {
            float xk = x[gi * DIN + k];
            asum += xk * g_was6[k];
            dsum += xk * g_wad6[k];
        }
    }

    __syncthreads();
    for (int off = 1; off < SCAN_B; off <<= 1) {
        int t = (tid >= off) ? s[tid - off] : 0;
        __syncthreads();
        s[tid] += t;
        __syncthreads();
    }
    int pre = spre;
    if (gi < NN) {
        int o = s[tid] - cnt + pre;
        g_offsets[gi] = o;
        g_cursor[gi]  = o;
        g_ind[gi]     = (cnt > 0) ? 1.f : 0.f;
        g_asrc[gi]    = asum;
        g_adst[gi]    = dsum;
    }
    if (gi == 0) g_offsets[NN] = EE;
}

// scatter + logit/exp
__global__ void k_scatter(const void* __restrict__ ei, const float* __restrict__ ew,
                          int need_eid) {
    int e = blockIdx.x * blockDim.x + threadIdx.x;
    if (e >= EE) return;
    int s, d;
    if (g_is64) {
        const long long* p = (const long long*)ei;
        s = (int)p[e];
        d = (int)p[EE + e];
    } else {
        const int* p = (const int*)ei;
        s = p[e];
        d = p[EE + e];
    }
    float l = g_asrc[s] + g_adst[d] + g_cedge * ew[e];
    l = (l > 0.f) ? l : SLOPE * l;
    float ev = __expf(l);
    int pos = atomicAdd(&g_cursor[d], 1);
    g_edge[pos] = make_uint2((unsigned int)s, (unsigned int)__float_as_int(ev));
    if (need_eid) g_eidA[pos] = e;
}

// warp per dst node: denom pre-pass + GAT aggregation; stores invd
__global__ __launch_bounds__(256) void k_gat(const float* __restrict__ b_gat,
                                             int need_alpha) {
    int n = blockIdx.x * 8 + (threadIdx.x >> 5);
    if (n >= NN) return;
    int lane = threadIdx.x & 31;
    int off = g_offsets[n];
    int deg = g_offsets[n + 1] - off;

    float lsum = 0.f;
    for (int i = lane; i < deg; i += 32)
        lsum += __int_as_float(g_edge[off + i].y);
#pragma unroll
    for (int o = 16; o > 0; o >>= 1) lsum += __shfl_xor_sync(FULLM, lsum, o);
    float invd = 1.f / fmaxf(lsum, 1e-16f);
    if (lane == 0) g_invd[n] = invd;

    float4 acc = make_float4(0.f, 0.f, 0.f, 0.f);
    int i = 0;
    for (; i + 4 <= deg; i += 4) {
        uint2 e0 = g_edge[off + i];
        uint2 e1 = g_edge[off + i + 1];
        uint2 e2 = g_edge[off + i + 2];
        uint2 e3 = g_edge[off + i + 3];
        uint2 r0 = *(const uint2*)&g_hh[(size_t)e0.x * HID + lane * 4];
        uint2 r1 = *(const uint2*)&g_hh[(size_t)e1.x * HID + lane * 4];
        uint2 r2 = *(const uint2*)&g_hh[(size_t)e2.x * HID + lane * 4];
        uint2 r3 = *(const uint2*)&g_hh[(size_t)e3.x * HID + lane * 4];
        float a0 = __int_as_float(e0.y), a1 = __int_as_float(e1.y);
        float a2 = __int_as_float(e2.y), a3 = __int_as_float(e3.y);
        float4 f0 = h4_to_f4(r0), f1 = h4_to_f4(r1);
        float4 f2 = h4_to_f4(r2), f3 = h4_to_f4(r3);
        acc.x += a0 * f0.x + a1 * f1.x + a2 * f2.x + a3 * f3.x;
        acc.y += a0 * f0.y + a1 * f1.y + a2 * f2.y + a3 * f3.y;
        acc.z += a0 * f0.z + a1 * f1.z + a2 * f2.z + a3 * f3.z;
        acc.w += a0 * f0.w + a1 * f1.w + a2 * f2.w + a3 * f3.w;
    }
    for (; i < deg; i++) {
        uint2 e0 = g_edge[off + i];
        uint2 r0 = *(const uint2*)&g_hh[(size_t)e0.x * HID + lane * 4];
        float a0 = __int_as_float(e0.y);
        float4 f0 = h4_to_f4(r0);
        acc.x += a0 * f0.x; acc.y += a0 * f0.y;
        acc.z += a0 * f0.z; acc.w += a0 * f0.w;
    }

    float4 b4 = *(const float4*)&b_gat[lane * 4];
    float4 r;
    r.x = fmaxf(acc.x * invd + b4.x, 0.f);
    r.y = fmaxf(acc.y * invd + b4.y, 0.f);
    r.z = fmaxf(acc.z * invd + b4.z, 0.f);
    r.w = fmaxf(acc.w * invd + b4.w, 0.f);
    *(uint2*)&g_h1h[(size_t)n * HID + lane * 4] = f4_to_h4(r);

    if (need_alpha) {
        for (int j = lane; j < deg; j += 32)
            g_alphan[off + j] = __int_as_float(g_edge[off + j].y) * invd;
    }
}

// hx = ind[row] * (h1 @ w_gcn) via mma.sync m16n8k16
__global__ __launch_bounds__(256) void k_gemm_mma() {
    int base = blockIdx.x * 128;
    int w    = threadIdx.x >> 5;
    int lane = threadIdx.x & 31;
    int gid  = lane >> 2;
    int k0   = (lane & 3) * 2;
    int nr = base + w * 16 + gid;

    unsigned int A[8][4];
#pragma unroll
    for (int ks = 0; ks < 8; ks++) {
        int kc = ks * 16 + k0;
        A[ks][0] = *(const unsigned int*)&g_h1h[(size_t)nr * HID + kc];
        A[ks][1] = *(const unsigned int*)&g_h1h[(size_t)(nr + 8) * HID + kc];
        A[ks][2] = *(const unsigned int*)&g_h1h[(size_t)nr * HID + kc + 8];
        A[ks][3] = *(const unsigned int*)&g_h1h[(size_t)(nr + 8) * HID + kc + 8];
    }

    float ind0 = g_ind[nr];
    float ind1 = g_ind[nr + 8];

#pragma unroll
    for (int nt = 0; nt < 16; nt++) {
        float c0 = 0.f, c1 = 0.f, c2 = 0.f, c3 = 0.f;
#pragma unroll
        for (int ks = 0; ks < 8; ks++) {
            int idx = ((nt * 8 + ks) * 32 + lane) * 2;
            unsigned int b0 = g_wfrag[idx];
            unsigned int b1 = g_wfrag[idx + 1];
            asm volatile(
                "mma.sync.aligned.m16n8k16.row.col.f32.f16.f16.f32 "
                "{%0,%1,%2,%3}, {%4,%5,%6,%7}, {%8,%9}, {%0,%1,%2,%3};"
                : "+f"(c0), "+f"(c1), "+f"(c2), "+f"(c3)
                : "r"(A[ks][0]), "r"(A[ks][1]), "r"(A[ks][2]), "r"(A[ks][3]),
                  "r"(b0), "r"(b1));
        }
        int col = nt * 8 + k0;
        if (nr < NN) {
            __half2 p = __floats2half2_rn(c0 * ind0, c1 * ind0);
            *(unsigned int*)&g_hxh[(size_t)nr * HID + col] =
                *reinterpret_cast<unsigned int*>(&p);
        }
        if (nr + 8 < NN) {
            __half2 p = __floats2half2_rn(c2 * ind1, c3 * ind1);
            *(unsigned int*)&g_hxh[(size_t)(nr + 8) * HID + col] =
                *reinterpret_cast<unsigned int*>(&p);
        }
    }
}

// warp per dst node: GCN aggregation + head
__global__ __launch_bounds__(256) void k_gcn_out(
    const float* __restrict__ b_gcn, const float* __restrict__ w_out,
    const float* __restrict__ b_out, float* __restrict__ out) {
    int n = blockIdx.x * 8 + (threadIdx.x >> 5);
    if (n >= NN) return;
    int lane = threadIdx.x & 31;
    int off = g_offsets[n];
    int deg = g_offsets[n + 1] - off;
    float invd = g_invd[n];

    float4 acc = make_float4(0.f, 0.f, 0.f, 0.f);
    int i = 0;
    for (; i + 4 <= deg; i += 4) {
        uint2 e0 = g_edge[off + i];
        uint2 e1 = g_edge[off + i + 1];
        uint2 e2 = g_edge[off + i + 2];
        uint2 e3 = g_edge[off + i + 3];
        uint2 r0 = *(const uint2*)&g_hxh[(size_t)e0.x * HID + lane * 4];
        uint2 r1 = *(const uint2*)&g_hxh[(size_t)e1.x * HID + lane * 4];
        uint2 r2 = *(const uint2*)&g_hxh[(size_t)e2.x * HID + lane * 4];
        uint2 r3 = *(const uint2*)&g_hxh[(size_t)e3.x * HID + lane * 4];
        float a0 = __int_as_float(e0.y), a1 = __int_as_float(e1.y);
        float a2 = __int_as_float(e2.y), a3 = __int_as_float(e3.y);
        float4 f0 = h4_to_f4(r0), f1 = h4_to_f4(r1);
        float4 f2 = h4_to_f4(r2), f3 = h4_to_f4(r3);
        acc.x += a0 * f0.x + a1 * f1.x + a2 * f2.x + a3 * f3.x;
        acc.y += a0 * f0.y + a1 * f1.y + a2 * f2.y + a3 * f3.y;
        acc.z += a0 * f0.z + a1 * f1.z + a2 * f2.z + a3 * f3.z;
        acc.w += a0 * f0.w + a1 * f1.w + a2 * f2.w + a3 * f3.w;
    }
    for (; i < deg; i++) {
        uint2 e0 = g_edge[off + i];
        uint2 r0 = *(const uint2*)&g_hxh[(size_t)e0.x * HID + lane * 4];
        float a0 = __int_as_float(e0.y);
        float4 f0 = h4_to_f4(r0);
        acc.x += a0 * f0.x; acc.y += a0 * f0.y;
        acc.z += a0 * f0.z; acc.w += a0 * f0.w;
    }

    float4 b4 = *(const float4*)&b_gcn[lane * 4];
    float4 h2;
    h2.x = fmaxf(acc.x * invd + b4.x, 0.f);
    h2.y = fmaxf(acc.y * invd + b4.y, 0.f);
    h2.z = fmaxf(acc.z * invd + b4.z, 0.f);
    h2.w = fmaxf(acc.w * invd + b4.w, 0.f);

    int jc = lane * 4;
    float v0 = h2.x * w_out[(jc + 0) * 2] + h2.y * w_out[(jc + 1) * 2]
             + h2.z * w_out[(jc + 2) * 2] + h2.w * w_out[(jc + 3) * 2];
    float v1 = h2.x * w_out[(jc + 0) * 2 + 1] + h2.y * w_out[(jc + 1) * 2 + 1]
             + h2.z * w_out[(jc + 2) * 2 + 1] + h2.w * w_out[(jc + 3) * 2 + 1];
#pragma unroll
    for (int o = 16; o > 0; o >>= 1) {
        v0 += __shfl_xor_sync(FULLM, v0, o);
        v1 += __shfl_xor_sync(FULLM, v1, o);
    }
    if (lane == 0) {
        out[n * 2 + 0] = v0 + b_out[0];
        out[n * 2 + 1] = v1 + b_out[1];
    }
}

__global__ void k_copy_ei_f(const void* __restrict__ ei, float* __restrict__ dst) {
    int i = blockIdx.x * blockDim.x + threadIdx.x;
    if (i >= 2 * EE) return;
    if (g_is64) dst[i] = (float)((const long long*)ei)[i];
    else        dst[i] = (float)((const int*)ei)[i];
}

__global__ void k_copy_alpha(float* __restrict__ dst) {
    int i = blockIdx.x * blockDim.x + threadIdx.x;
    if (i < EE) dst[g_eidA[i]] = g_alphan[i];
}

// ---------------- launch ----------------
extern "C" void kernel_launch(void* const* d_in, const int* in_sizes, int n_in,
                              void* d_out, int out_size) {
    static cudaStream_t s1 = 0, s2 = 0, s3 = 0;
    static cudaEvent_t evStart = 0, evNT = 0, evW = 0, evGat = 0, evAl = 0, evEi = 0;
    if (s1 == 0) {
        cudaStreamCreateWithFlags(&s1, cudaStreamNonBlocking);
        cudaStreamCreateWithFlags(&s2, cudaStreamNonBlocking);
        cudaStreamCreateWithFlags(&s3, cudaStreamNonBlocking);
        cudaEventCreateWithFlags(&evStart, cudaEventDisableTiming);
        cudaEventCreateWithFlags(&evNT, cudaEventDisableTiming);
        cudaEventCreateWithFlags(&evW,  cudaEventDisableTiming);
        cudaEventCreateWithFlags(&evGat, cudaEventDisableTiming);
        cudaEventCreateWithFlags(&evAl, cudaEventDisableTiming);
        cudaEventCreateWithFlags(&evEi, cudaEventDisableTiming);
    }

    int iei, iew, iwg, ias, iad, iwe, iae, ibg, iwgcn, ibgcn, iwo, ibo;
    if (in_sizes[1] == 2 * EE) {
        iei = 1; iew = 2; iwg = 3; ias = 4; iad = 5; iwe = 6; iae = 7;
        ibg = 8; iwgcn = 9; ibgcn = 10; iwo = 11; ibo = 12;
    } else {
        iew = 1; iwg = 2; ias = 3; iad = 4; iwe = 5; iae = 6; ibg = 7;
        iwgcn = 8; ibgcn = 9; iwo = 10; ibo = 11; iei = 12;
    }

    const float* x        = (const float*)d_in[0];
    const void*  ei       = d_in[iei];
    const float* ew       = (const float*)d_in[iew];
    const float* w_gat    = (const float*)d_in[iwg];
    const float* att_src  = (const float*)d_in[ias];
    const float* att_dst  = (const float*)d_in[iad];
    const float* w_edge   = (const float*)d_in[iwe];
    const float* att_edge = (const float*)d_in[iae];
    const float* b_gat    = (const float*)d_in[ibg];
    const float* w_gcn    = (const float*)d_in[iwgcn];
    const float* b_gcn    = (const float*)d_in[ibgcn];
    const float* w_out    = (const float*)d_in[iwo];
    const float* b_out    = (const float*)d_in[ibo];
    float*       out      = (float*)d_out;

    int rem = out_size - NN * OUTD;
    int need_alpha = (rem == EE || rem == 3 * EE) ? 1 : 0;

    // fork point at capture start
    cudaEventRecord(evStart, 0);

    // side stream 1: node transform (independent of edge chain)
    cudaStreamWaitEvent(s1, evStart, 0);
    k_node_transform<<<(NN + 31) / 32, 256, 0, s1>>>(x, w_gat);
    cudaEventRecord(evNT, s1);

    // side stream 2: w_gcn fragment prep (+ optional ei copy, both independent)
    cudaStreamWaitEvent(s2, evStart, 0);
    k_wprep<<<16, 256, 0, s2>>>(w_gcn);
    if (rem == 3 * EE)
        k_copy_ei_f<<<(2 * EE + 255) / 256, 256, 0, s2>>>(ei, out + NN * OUTD);
    cudaEventRecord(evW, s2);

    // main chain
    k_pre<<<(NN + 255) / 256, 256>>>((const int*)ei, w_edge, att_edge,
                                     w_gat, att_src, att_dst);
    k_convert<<<(EE / 2 + 255) / 256, 256>>>(ei);
    k_bsum<<<NB, 256>>>();
    k_scanall<<<NB, SCAN_B>>>(x);
    k_scatter<<<(EE + 255) / 256, 256>>>(ei, ew, need_alpha);

    cudaStreamWaitEvent(0, evNT, 0);   // gat reads g_hh
    k_gat<<<NN / 8, 256>>>(b_gat, need_alpha);
    cudaEventRecord(evGat, 0);

    // side stream 3: alpha copy overlaps gemm+gcn
    if (need_alpha) {
        float* adst_out = (rem == EE) ? (out + NN * OUTD) : (out + NN * OUTD + 2 * EE);
        cudaStreamWaitEvent(s3, evGat, 0);
        k_copy_alpha<<<(EE + 255) / 256, 256, 0, s3>>>(adst_out);
        cudaEventRecord(evAl, s3);
    }

    cudaStreamWaitEvent(0, evW, 0);    // gemm reads g_wfrag
    k_gemm_mma<<<NNP / 128, 256>>>();
    k_gcn_out<<<NN / 8, 256>>>(b_gcn, w_out, b_out, out);

    if (need_alpha) cudaStreamWaitEvent(0, evAl, 0);
}